// round 6
// baseline (speedup 1.0000x reference)
#include <cuda_runtime.h>
#include <cuda_bf16.h>
#include <math.h>
#include <stdint.h>

#define BB 64
#define TT 2048
#define DIM 256
#define VOCAB 32000
#define TAIL 192
#define EPS_CUT 1e-9f

__device__ float d_w[BB * TT];
__device__ int   d_t0[BB];
__device__ float d_hT[BB * DIM];   // [b][k] fp32

// packed f32x2 FMA: c = a*b + c (elementwise on 2 packed fp32)
#define FMA2(c, a, b) \
    asm("fma.rn.f32x2 %0, %1, %2, %0;" : "+l"(c) : "l"(a), "l"(b))

// ---------------------------------------------------------------------------
// K1: parallel tail gate scan, fixed TAIL=192. 512 thr: 8 thr/token,
// 3 passes of 64 tokens; warp 0 then does a shuffle suffix-product scan.
// ---------------------------------------------------------------------------
__global__ void __launch_bounds__(512) k_scan(
        const int* __restrict__ x, const float* __restrict__ emb,
        const float* __restrict__ Wg, const float* __restrict__ Wg_b) {
    int b = blockIdx.x, tid = threadIdx.x;
    int slotg = tid >> 3, sub = tid & 7;
    __shared__ float g_sh[TAIL];
    float gb = Wg_b[0];

    const float4* w4 = (const float4*)Wg;
    float4 wv[8];
#pragma unroll
    for (int i = 0; i < 8; i++) wv[i] = w4[sub * 8 + i];

#pragma unroll
    for (int p = 0; p < 3; p++) {
        int slot = p * 64 + slotg;
        int xv = x[b * TT + (TT - TAIL + slot)];
        const float4* e4 = (const float4*)(emb + (size_t)xv * DIM);
        float z = 0.f;
#pragma unroll
        for (int i = 0; i < 8; i++) {
            float4 e = e4[sub * 8 + i];
            z += e.x * wv[i].x + e.y * wv[i].y + e.z * wv[i].z + e.w * wv[i].w;
        }
        z += __shfl_xor_sync(0xffffffffu, z, 1);
        z += __shfl_xor_sync(0xffffffffu, z, 2);
        z += __shfl_xor_sync(0xffffffffu, z, 4);
        if (sub == 0) g_sh[slot] = 1.f / (1.f + expf(-(z + gb)));
    }
    __syncthreads();

    if (tid < 32) {
        int l = tid;
        float P = 1.f;
#pragma unroll
        for (int j = 0; j < 6; j++) P *= g_sh[l * 6 + j];
        float S = P;
#pragma unroll
        for (int off = 1; off < 32; off <<= 1) {
            float v = __shfl_down_sync(0xffffffffu, S, off);
            if (l + off < 32) S *= v;
        }
        float Q = __shfl_down_sync(0xffffffffu, S, 1);
        if (l == 31) Q = 1.f;
        float Sc = Q;
        int myt0 = TT;
#pragma unroll
        for (int j = 5; j >= 0; j--) {
            int slot = l * 6 + j;
            int t = TT - TAIL + slot;
            float g = g_sh[slot];
            d_w[b * TT + t] = (1.f - g) * Sc;
            if (Sc >= EPS_CUT) myt0 = t;
            Sc *= g;
        }
#pragma unroll
        for (int off = 16; off; off >>= 1) {
            int v = __shfl_xor_sync(0xffffffffu, myt0, off);
            myt0 = v < myt0 ? v : myt0;
        }
        if (l == 0) d_t0[b] = (myt0 == TT) ? (TT - TAIL) : myt0;
    }
}

// ---------------------------------------------------------------------------
// K2: hT[b,:] = sum_{t>=t0} w_t * tanh(W @ emb[x[b,t]] + Wb)
// Grid (2,64), 512 thr; depth-8 smem ring (LDG 8 steps ahead, STS 5 ahead)
// hides the emb-gather latency behind 3 iterations. Writes fp32 d_hT.
// ---------------------------------------------------------------------------
__global__ void __launch_bounds__(512, 1) k_main(
        const int* __restrict__ x, const float* __restrict__ emb,
        const float* __restrict__ W, const float* __restrict__ Wb) {
    int dh = blockIdx.x, b = blockIdx.y, tid = threadIdx.x;
    int lane = tid & 31, w = tid >> 5;
    int kq = lane & 3;
    int dg = dh * 128 + w * 8 + (lane >> 2);

    float wreg[64];
    const float4* W4 = (const float4*)(W + (size_t)dg * DIM + kq * 64);
#pragma unroll
    for (int i = 0; i < 16; i++) {
        float4 v = W4[i];
        wreg[4 * i + 0] = v.x; wreg[4 * i + 1] = v.y;
        wreg[4 * i + 2] = v.z; wreg[4 * i + 3] = v.w;
    }
    float wb = Wb[dg];
    int t0 = d_t0[b];
    int L = TT - t0;

    __shared__ float e_s[8][DIM];
#pragma unroll
    for (int s = 0; s < 5; s++)
        if (s < L && tid < DIM)
            e_s[s][tid] = emb[(size_t)x[b * TT + (TT - 1 - s)] * DIM + tid];
    float q0 = 0.f, q1 = 0.f, q2 = 0.f;
    if (tid < DIM) {
        if (5 < L) q0 = emb[(size_t)x[b * TT + TT - 6] * DIM + tid];
        if (6 < L) q1 = emb[(size_t)x[b * TT + TT - 7] * DIM + tid];
        if (7 < L) q2 = emb[(size_t)x[b * TT + TT - 8] * DIM + tid];
    }
    __syncthreads();

    float acc = 0.f;
    for (int i = 0; i < L; i++) {
        int t = TT - 1 - i;
        if (i + 5 < L && tid < DIM) e_s[(i + 5) & 7][tid] = q0;
        q0 = q1; q1 = q2; q2 = 0.f;
        if (i + 8 < L && tid < DIM)
            q2 = emb[(size_t)x[b * TT + (t - 8)] * DIM + tid];

        const float4* ev = (const float4*)&e_s[i & 7][kq * 64];
        float s0 = 0.f, s1 = 0.f, s2 = 0.f, s3 = 0.f;
#pragma unroll
        for (int j = 0; j < 16; j++) {
            float4 e = ev[j];
            s0 = fmaf(wreg[4 * j + 0], e.x, s0);
            s1 = fmaf(wreg[4 * j + 1], e.y, s1);
            s2 = fmaf(wreg[4 * j + 2], e.z, s2);
            s3 = fmaf(wreg[4 * j + 3], e.w, s3);
        }
        float ps = (s0 + s1) + (s2 + s3);
        ps += __shfl_xor_sync(0xffffffffu, ps, 1);
        ps += __shfl_xor_sync(0xffffffffu, ps, 2);
        acc = fmaf(d_w[b * TT + t], tanhf(ps + wb), acc);
        __syncthreads();
    }

    if ((lane & 3) == 0) d_hT[b * DIM + dg] = acc;
}

// ---------------------------------------------------------------------------
// K3: out[b][v] = hT[b,:].head_w[v,:] + head_b[v], packed f32x2 FMA.
// Block: 256 v x 64 b, 256 thr; thread tile 4 v x 16 b (acc = 32 f32x2).
// Warp (w): wb=w&3 -> b range [wb*16, wb*16+16); wv=w>>2 -> v half.
// smem: hTs [256 k][64 b] (stride 66, pad for bank/align);
//       sWd [16 k][512] head_w values DUPLICATED ((w,w) pairs) so LDS.64
//       feeds FMA2's lane-varying operand; hT pairs come from broadcast
//       LDS.64 (warp-uniform address -> no crossbar pressure).
// Crossbar: 256B/8-reuse = 32B per FFMA2 instr <= 64B budget -> FMA2-bound.
// ---------------------------------------------------------------------------
#define VBLK 256
#define KC 16
#define HS 66
#define WS 514
#define SMEM_HEAD ((DIM * HS + 2 * KC * WS) * 4)

__global__ void __launch_bounds__(256, 1) k_head(
        const float* __restrict__ hw, const float* __restrict__ hb,
        float* __restrict__ out) {
    extern __shared__ float sm[];
    float* hTs = sm;                   // [256][HS]
    float* sW0 = sm + DIM * HS;        // [KC][WS]
    float* sW1 = sW0 + KC * WS;

    int tid = threadIdx.x;
    int w = tid >> 5, tv = tid & 31;
    int wb = w & 3, wv = w >> 2;
    int vbase = blockIdx.x * VBLK;

    // ---- build hTs [k][b] (one-time, 64KB) ----
#pragma unroll
    for (int it = 0; it < 16; it++) {
        int idx4 = it * 256 + tid;
        int bb = idx4 >> 6, k4 = idx4 & 63;
        float4 h = *(const float4*)&d_hT[bb * DIM + k4 * 4];
        hTs[(k4 * 4 + 0) * HS + bb] = h.x;
        hTs[(k4 * 4 + 1) * HS + bb] = h.y;
        hTs[(k4 * 4 + 2) * HS + bb] = h.z;
        hTs[(k4 * 4 + 3) * HS + bb] = h.w;
    }
    // ---- stage chunk 0 into sW0 (transposed + duplicated) ----
#pragma unroll
    for (int it = 0; it < 4; it++) {
        int idx4 = it * 256 + tid;
        int r = idx4 >> 2, c4 = idx4 & 3;
        float4 f = *(const float4*)&hw[(size_t)(vbase + r) * DIM + c4 * 4];
        float vals[4] = {f.x, f.y, f.z, f.w};
#pragma unroll
        for (int j2 = 0; j2 < 4; j2++) {
            float* d2 = &sW0[(c4 * 4 + j2) * WS + 2 * r];
            d2[0] = vals[j2]; d2[1] = vals[j2];
        }
    }
    __syncthreads();

    unsigned long long acc[4][8];
#pragma unroll
    for (int j = 0; j < 4; j++)
#pragma unroll
        for (int p = 0; p < 8; p++) acc[j][p] = 0ull;

    for (int ch = 0; ch < 16; ch++) {
        int kb = ch * KC;
        // prefetch next chunk of head_w into registers
        float4 pf[4];
        if (ch < 15) {
#pragma unroll
            for (int it = 0; it < 4; it++) {
                int idx4 = it * 256 + tid;
                int r = idx4 >> 2, c4 = idx4 & 3;
                pf[it] = *(const float4*)&hw[(size_t)(vbase + r) * DIM +
                                             (kb + KC) + c4 * 4];
            }
        }
        const float* buf = (ch & 1) ? sW1 : sW0;
#pragma unroll
        for (int kk = 0; kk < KC; kk++) {
            unsigned long long wd[4];
#pragma unroll
            for (int j = 0; j < 4; j++)
                wd[j] = *(const unsigned long long*)
                        &buf[kk * WS + wv * 256 + j * 64 + 2 * tv];
            unsigned long long hp[8];
            const float* hrow = &hTs[(kb + kk) * HS + wb * 16];
#pragma unroll
            for (int p = 0; p < 8; p++)
                hp[p] = *(const unsigned long long*)&hrow[2 * p];
#pragma unroll
            for (int j = 0; j < 4; j++)
#pragma unroll
                for (int p = 0; p < 8; p++)
                    FMA2(acc[j][p], wd[j], hp[p]);
        }
        if (ch < 15) {
            __syncthreads();
            float* dst = (ch & 1) ? sW0 : sW1;
#pragma unroll
            for (int it = 0; it < 4; it++) {
                int idx4 = it * 256 + tid;
                int r = idx4 >> 2, c4 = idx4 & 3;
                float vals[4] = {pf[it].x, pf[it].y, pf[it].z, pf[it].w};
#pragma unroll
                for (int j2 = 0; j2 < 4; j2++) {
                    float* d2 = &dst[(c4 * 4 + j2) * WS + 2 * r];
                    d2[0] = vals[j2]; d2[1] = vals[j2];
                }
            }
            __syncthreads();
        }
    }

    // ---- epilogue: unpack pairs, add bias, coalesced STG ----
#pragma unroll
    for (int j = 0; j < 4; j++) {
        int v = vbase + wv * 128 + j * 32 + tv;
        float bias = hb[v];
#pragma unroll
        for (int p = 0; p < 8; p++) {
            float lo, hi;
            asm("mov.b64 {%0,%1}, %2;" : "=f"(lo), "=f"(hi) : "l"(acc[j][p]));
            int b = wb * 16 + 2 * p;
            out[(size_t)b * VOCAB + v] = lo + bias;
            out[(size_t)(b + 1) * VOCAB + v] = hi + bias;
        }
    }
}

// ---------------------------------------------------------------------------
extern "C" void kernel_launch(void* const* d_in, const int* in_sizes, int n_in,
                              void* d_out, int out_size) {
    const int*   x      = (const int*)d_in[0];
    const float* emb    = (const float*)d_in[1];
    const float* W_w    = (const float*)d_in[2];
    const float* W_b    = (const float*)d_in[3];
    const float* Wg_w   = (const float*)d_in[4];
    const float* Wg_b   = (const float*)d_in[5];
    const float* head_w = (const float*)d_in[6];
    const float* head_b = (const float*)d_in[7];
    float* out = (float*)d_out;

    k_scan<<<BB, 512>>>(x, emb, Wg_w, Wg_b);
    k_main<<<dim3(2, BB), 512>>>(x, emb, W_w, W_b);
    cudaFuncSetAttribute(k_head, cudaFuncAttributeMaxDynamicSharedMemorySize,
                         SMEM_HEAD);
    k_head<<<VOCAB / VBLK, 256, SMEM_HEAD>>>(head_w, head_b, out);
}

// round 8
// speedup vs baseline: 1.4423x; 1.4423x over previous
#include <cuda_runtime.h>
#include <cuda_bf16.h>
#include <math.h>
#include <stdint.h>

#define BB 64
#define TT 2048
#define DIM 256
#define VOCAB 32000
#define TAIL 96
#define EPS_CUT 1e-7f

__device__ float d_w[BB * TT];
__device__ int   d_t0[BB];
__device__ float d_hT[BB * DIM];   // [b][k] fp32

// packed f32x2 FMA: c = a*b + c (elementwise on 2 packed fp32)
#define FMA2(c, a, b) \
    asm("fma.rn.f32x2 %0, %1, %2, %0;" : "+l"(c) : "l"(a), "l"(b))
__device__ __forceinline__ float2 unpack2(unsigned long long v) {
    float2 r;
    asm("mov.b64 {%0,%1}, %2;" : "=f"(r.x), "=f"(r.y) : "l"(v));
    return r;
}
__device__ __forceinline__ unsigned long long dup2(float s) {
    unsigned long long d;
    asm("mov.b64 %0, {%1,%1};" : "=l"(d) : "f"(s));
    return d;
}

// ---------------------------------------------------------------------------
// K1: tail gate scan, TAIL=96, one shot. 768 thr: 8 thr/token, all gathers
// issued concurrently; warp 0 does a shuffle suffix-product scan (3 g/lane).
// ---------------------------------------------------------------------------
__global__ void __launch_bounds__(768) k_scan(
        const int* __restrict__ x, const float* __restrict__ emb,
        const float* __restrict__ Wg, const float* __restrict__ Wg_b) {
    int b = blockIdx.x, tid = threadIdx.x;
    int tok = tid >> 3, sub = tid & 7;
    __shared__ float g_sh[TAIL];
    float gb = Wg_b[0];

    const float4* w4 = (const float4*)Wg;
    float4 wv[8];
#pragma unroll
    for (int i = 0; i < 8; i++) wv[i] = w4[sub * 8 + i];

    {
        int xv = x[b * TT + (TT - TAIL + tok)];
        const float4* e4 = (const float4*)(emb + (size_t)xv * DIM);
        float z = 0.f;
#pragma unroll
        for (int i = 0; i < 8; i++) {
            float4 e = e4[sub * 8 + i];
            z += e.x * wv[i].x + e.y * wv[i].y + e.z * wv[i].z + e.w * wv[i].w;
        }
        z += __shfl_xor_sync(0xffffffffu, z, 1);
        z += __shfl_xor_sync(0xffffffffu, z, 2);
        z += __shfl_xor_sync(0xffffffffu, z, 4);
        if (sub == 0) g_sh[tok] = 1.f / (1.f + expf(-(z + gb)));
    }
    __syncthreads();

    if (tid < 32) {
        int l = tid;
        float P = g_sh[l * 3] * g_sh[l * 3 + 1] * g_sh[l * 3 + 2];
        float S = P;
#pragma unroll
        for (int off = 1; off < 32; off <<= 1) {
            float v = __shfl_down_sync(0xffffffffu, S, off);
            if (l + off < 32) S *= v;
        }
        float Q = __shfl_down_sync(0xffffffffu, S, 1);
        if (l == 31) Q = 1.f;
        float Sc = Q;
        int myt0 = TT;
#pragma unroll
        for (int j = 2; j >= 0; j--) {
            int slot = l * 3 + j;
            int t = TT - TAIL + slot;
            float g = g_sh[slot];
            d_w[b * TT + t] = (1.f - g) * Sc;
            if (Sc >= EPS_CUT) myt0 = t;
            Sc *= g;
        }
#pragma unroll
        for (int off = 16; off; off >>= 1) {
            int v = __shfl_xor_sync(0xffffffffu, myt0, off);
            myt0 = v < myt0 ? v : myt0;
        }
        if (l == 0) d_t0[b] = (myt0 == TT) ? (TT - TAIL) : myt0;
    }
}

// ---------------------------------------------------------------------------
// K2: hT[b,:] = sum_{t>=t0} w_t * tanh(W @ emb[x[b,t]] + Wb)
// Grid (2,64), 512 thr; depth-8 smem ring (LDG 8 ahead, STS 5 ahead).
// e_s quarters PADDED to 68 floats (banks 0/4/8/12 -> conflict-free LDS.128;
// the old kq*64 layout was a hidden 4-way conflict = 2x iter cost).
// Inner product in packed f32x2.
// ---------------------------------------------------------------------------
#define QP 68                      // padded quarter stride (floats)
__device__ __forceinline__ int eoff(int c) { return (c >> 6) * QP + (c & 63); }

__global__ void __launch_bounds__(512, 1) k_main(
        const int* __restrict__ x, const float* __restrict__ emb,
        const float* __restrict__ W, const float* __restrict__ Wb) {
    int dh = blockIdx.x, b = blockIdx.y, tid = threadIdx.x;
    int lane = tid & 31, w = tid >> 5;
    int kq = lane & 3;
    int dg = dh * 128 + w * 8 + (lane >> 2);

    unsigned long long wp[32];      // 64 floats as 32 packed pairs
    const ulonglong2* W2 = (const ulonglong2*)(W + (size_t)dg * DIM + kq * 64);
#pragma unroll
    for (int i = 0; i < 16; i++) {
        ulonglong2 v = W2[i];
        wp[2 * i] = v.x; wp[2 * i + 1] = v.y;
    }
    float wb = Wb[dg];
    int t0 = d_t0[b];
    int L = TT - t0;

    __shared__ float e_s[8][4 * QP];
#pragma unroll
    for (int s = 0; s < 5; s++)
        if (s < L && tid < DIM)
            e_s[s][eoff(tid)] = emb[(size_t)x[b * TT + (TT - 1 - s)] * DIM + tid];
    float q0 = 0.f, q1 = 0.f, q2 = 0.f;
    if (tid < DIM) {
        if (5 < L) q0 = emb[(size_t)x[b * TT + TT - 6] * DIM + tid];
        if (6 < L) q1 = emb[(size_t)x[b * TT + TT - 7] * DIM + tid];
        if (7 < L) q2 = emb[(size_t)x[b * TT + TT - 8] * DIM + tid];
    }
    __syncthreads();

    float acc = 0.f;
    for (int i = 0; i < L; i++) {
        int t = TT - 1 - i;
        if (i + 5 < L && tid < DIM) e_s[(i + 5) & 7][eoff(tid)] = q0;
        q0 = q1; q1 = q2; q2 = 0.f;
        if (i + 8 < L && tid < DIM)
            q2 = emb[(size_t)x[b * TT + (t - 8)] * DIM + tid];

        const ulonglong2* ev = (const ulonglong2*)(&e_s[i & 7][kq * QP]);
        unsigned long long a0 = 0, a1 = 0, a2 = 0, a3 = 0;
#pragma unroll
        for (int j = 0; j < 16; j += 2) {
            ulonglong2 e0 = ev[j];
            FMA2(a0, wp[2 * j], e0.x);
            FMA2(a1, wp[2 * j + 1], e0.y);
            ulonglong2 e1 = ev[j + 1];
            FMA2(a2, wp[2 * j + 2], e1.x);
            FMA2(a3, wp[2 * j + 3], e1.y);
        }
        float2 f0 = unpack2(a0), f1 = unpack2(a1);
        float2 f2 = unpack2(a2), f3 = unpack2(a3);
        float ps = ((f0.x + f0.y) + (f1.x + f1.y)) +
                   ((f2.x + f2.y) + (f3.x + f3.y));
        ps += __shfl_xor_sync(0xffffffffu, ps, 1);
        ps += __shfl_xor_sync(0xffffffffu, ps, 2);
        acc = fmaf(d_w[b * TT + t], tanhf(ps + wb), acc);
        __syncthreads();
    }

    if ((lane & 3) == 0) d_hT[b * DIM + dg] = acc;
}

// ---------------------------------------------------------------------------
// K3: out[b][v] = hT[b,:].head_w[v,:] + head_b[v].
// R1's measured-good structure, fixed: b split 2 (32 b/CTA, 250 CTAs ->
// ~2 CTAs/SM), f32x2 over natural v-pairs from hws (LDS.128 reinterpret),
// b-values duplicated via mov.b64 (ALU pipe, hidden under FMA).
// Thread tile 8v x 4b = 16 f32x2 accumulators.
// ---------------------------------------------------------------------------
#define HS 36                       // hTs stride (floats), 16B-aligned
#define WSS 260                     // hws stride
#define SMEM_HEAD ((DIM * HS + 2 * 16 * WSS) * 4)

__global__ void __launch_bounds__(256, 2) k_head(
        const float* __restrict__ hw, const float* __restrict__ hb,
        float* __restrict__ out) {
    extern __shared__ float sm[];
    float* hTs = sm;                   // [256][HS] (32 b + pad)
    float* hws0 = sm + DIM * HS;       // [16][WSS]
    float* hws1 = hws0 + 16 * WSS;

    int tid = threadIdx.x;
    int w = tid >> 5, lane = tid & 31;
    int vbase = (blockIdx.x >> 1) * 256;
    int boff = (blockIdx.x & 1) * 32;
    int v0l = lane * 8;
    int b0 = w * 4;

    // hTs[k][b]: coalesced LDG, scattered STS (one-time)
#pragma unroll
    for (int it = 0; it < 32; it++) {
        int idx = it * 256 + tid;
        int bb = idx >> 8, k = idx & 255;
        hTs[k * HS + bb] = d_hT[(boff + bb) * DIM + k];
    }
    // stage hw chunk 0
#pragma unroll
    for (int r = 0; r < 16; r++) {
        int idx = r * 256 + tid;
        int vl = idx >> 4, kk = idx & 15;
        hws0[kk * WSS + vl] = hw[(size_t)(vbase + vl) * DIM + kk];
    }
    __syncthreads();

    unsigned long long acc[4][4];
#pragma unroll
    for (int vp = 0; vp < 4; vp++)
#pragma unroll
        for (int bi = 0; bi < 4; bi++) acc[vp][bi] = 0ull;

    for (int ch = 0; ch < 16; ch++) {
        int kb = ch * 16;
        float pf[16];
        if (ch < 15) {
#pragma unroll
            for (int r = 0; r < 16; r++) {
                int idx = r * 256 + tid;
                int vl = idx >> 4, kk = idx & 15;
                pf[r] = hw[(size_t)(vbase + vl) * DIM + kb + 16 + kk];
            }
        }
        const float* buf = (ch & 1) ? hws1 : hws0;
#pragma unroll
        for (int kk = 0; kk < 16; kk++) {
            float4 t4 = *(const float4*)&hTs[(kb + kk) * HS + b0];
            unsigned long long td[4] = {dup2(t4.x), dup2(t4.y),
                                        dup2(t4.z), dup2(t4.w)};
            ulonglong2 h01 = *(const ulonglong2*)&buf[kk * WSS + v0l];
            ulonglong2 h23 = *(const ulonglong2*)&buf[kk * WSS + v0l + 4];
            unsigned long long hv2[4] = {h01.x, h01.y, h23.x, h23.y};
#pragma unroll
            for (int vp = 0; vp < 4; vp++)
#pragma unroll
                for (int bi = 0; bi < 4; bi++)
                    FMA2(acc[vp][bi], hv2[vp], td[bi]);
        }
        if (ch < 15) {
            __syncthreads();
            float* dst = (ch & 1) ? hws0 : hws1;
#pragma unroll
            for (int r = 0; r < 16; r++) {
                int idx = r * 256 + tid;
                int vl = idx >> 4, kk = idx & 15;
                dst[kk * WSS + vl] = pf[r];
            }
            __syncthreads();
        }
    }

    // epilogue: float2 stores (v-pairs contiguous), add bias
#pragma unroll
    for (int vp = 0; vp < 4; vp++) {
        int v = vbase + v0l + vp * 2;
        float2 bias = *(const float2*)&hb[v];
#pragma unroll
        for (int bi = 0; bi < 4; bi++) {
            float2 r = unpack2(acc[vp][bi]);
            r.x += bias.x; r.y += bias.y;
            *(float2*)&out[(size_t)(boff + b0 + bi) * VOCAB + v] = r;
        }
    }
}

// ---------------------------------------------------------------------------
extern "C" void kernel_launch(void* const* d_in, const int* in_sizes, int n_in,
                              void* d_out, int out_size) {
    const int*   x      = (const int*)d_in[0];
    const float* emb    = (const float*)d_in[1];
    const float* W_w    = (const float*)d_in[2];
    const float* W_b    = (const float*)d_in[3];
    const float* Wg_w   = (const float*)d_in[4];
    const float* Wg_b   = (const float*)d_in[5];
    const float* head_w = (const float*)d_in[6];
    const float* head_b = (const float*)d_in[7];
    float* out = (float*)d_out;

    k_scan<<<BB, 768>>>(x, emb, Wg_w, Wg_b);
    k_main<<<dim3(2, BB), 512>>>(x, emb, W_w, W_b);
    cudaFuncSetAttribute(k_head, cudaFuncAttributeMaxDynamicSharedMemorySize,
                         SMEM_HEAD);
    k_head<<<250, 256, SMEM_HEAD>>>(head_w, head_b, out);
}

// round 12
// speedup vs baseline: 1.5028x; 1.0419x over previous
#include <cuda_runtime.h>
#include <cuda_bf16.h>
#include <math.h>
#include <stdint.h>

#define BB 64
#define TT 2048
#define DIM 256
#define VOCAB 32000
#define TAILF 96
#define EPS_CUT 1e-7f

__device__ float d_hT[BB * DIM];   // [b][k] fp32

// packed f32x2 FMA: c = a*b + c (elementwise on 2 packed fp32)
#define FMA2(c, a, b) \
    asm("fma.rn.f32x2 %0, %1, %2, %0;" : "+l"(c) : "l"(a), "l"(b))
__device__ __forceinline__ float2 unpack2(unsigned long long v) {
    float2 r;
    asm("mov.b64 {%0,%1}, %2;" : "=f"(r.x), "=f"(r.y) : "l"(v));
    return r;
}
__device__ __forceinline__ unsigned long long dup2(float s) {
    unsigned long long d;
    asm("mov.b64 %0, {%1,%1};" : "=l"(d) : "f"(s));
    return d;
}

// ---------------------------------------------------------------------------
// K1 (fused scan+main): per (dh,b) block, 512 threads.
//  P0: stage x tail indices to smem
//  P1: gather all 96 tail emb rows into padded smem (one shot, max MLP)
//  P2: 96 gate dots from smem (16 warps x 6 tokens)
//  P3: warp 0 suffix-product scan -> w_sh[96], t0
//  P4: accumulation loop, all operands in smem/regs, NO barriers in loop
// Row layout: 4 quarters of 64 floats padded to 68 (stride 272/row) ->
// conflict-free LDS.128 across the 4 kq groups.
// ---------------------------------------------------------------------------
#define RQP 68
#define ROWS 272
#define DSMEM_F (TAILF * ROWS * 4)

__global__ void __launch_bounds__(512, 1) k_fused(
        const int* __restrict__ x, const float* __restrict__ emb,
        const float* __restrict__ W, const float* __restrict__ Wb,
        const float* __restrict__ Wg, const float* __restrict__ Wg_b) {
    extern __shared__ float e_s[];             // [96][272]
    __shared__ float g_sh[TAILF], w_sh[TAILF];
    __shared__ int s_x[TAILF];
    __shared__ int s_t0;

    int dh = blockIdx.x, b = blockIdx.y, tid = threadIdx.x;
    int lane = tid & 31, w = tid >> 5;
    int kq = lane & 3;
    int dg = dh * 128 + w * 8 + (lane >> 2);

    // W row quarter in packed-pair registers
    unsigned long long wp[32];
    const ulonglong2* W2 = (const ulonglong2*)(W + (size_t)dg * DIM + kq * 64);
#pragma unroll
    for (int i = 0; i < 16; i++) {
        ulonglong2 v = W2[i];
        wp[2 * i] = v.x; wp[2 * i + 1] = v.y;
    }
    float wb = Wb[dg];
    float gb = Wg_b[0];
    // Wg slice for the gate dot (lane covers 8 dims)
    float4 wg0 = ((const float4*)Wg)[lane * 2];
    float4 wg1 = ((const float4*)Wg)[lane * 2 + 1];

    // ---- P0: stage token ids ----
    if (tid < TAILF) s_x[tid] = x[b * TT + (TT - TAILF) + tid];
    __syncthreads();

    // ---- P1: gather 96 rows (6144 float4 over 512 threads = 12 each) ----
#pragma unroll
    for (int it = 0; it < 12; it++) {
        int idx4 = it * 512 + tid;
        int r = idx4 >> 6, c4 = idx4 & 63;
        float4 v = *(const float4*)&emb[(size_t)s_x[r] * DIM + c4 * 4];
        *(float4*)&e_s[r * ROWS + (c4 >> 4) * RQP + (c4 & 15) * 4] = v;
    }
    __syncthreads();

    // ---- P2: gate dots (warp wi -> tokens wi*6..wi*6+5) ----
#pragma unroll
    for (int j = 0; j < 6; j++) {
        int r = w * 6 + j;
        const float* row = &e_s[r * ROWS + (lane >> 3) * RQP + ((lane * 8) & 63)];
        float4 a0 = *(const float4*)row;
        float4 a1 = *(const float4*)(row + 4);
        float z = a0.x * wg0.x + a0.y * wg0.y + a0.z * wg0.z + a0.w * wg0.w
                + a1.x * wg1.x + a1.y * wg1.y + a1.z * wg1.z + a1.w * wg1.w;
#pragma unroll
        for (int off = 16; off; off >>= 1)
            z += __shfl_xor_sync(0xffffffffu, z, off);
        if (lane == 0) g_sh[r] = 1.f / (1.f + expf(-(z + gb)));
    }
    __syncthreads();

    // ---- P3: suffix-product scan (warp 0, 3 gates/lane) ----
    if (tid < 32) {
        int l = tid;
        float P = g_sh[l * 3] * g_sh[l * 3 + 1] * g_sh[l * 3 + 2];
        float S = P;
#pragma unroll
        for (int off = 1; off < 32; off <<= 1) {
            float v = __shfl_down_sync(0xffffffffu, S, off);
            if (l + off < 32) S *= v;
        }
        float Q = __shfl_down_sync(0xffffffffu, S, 1);
        if (l == 31) Q = 1.f;
        float Sc = Q;
        int myt0 = TT;
#pragma unroll
        for (int j = 2; j >= 0; j--) {
            int slot = l * 3 + j;
            float g = g_sh[slot];
            w_sh[slot] = (1.f - g) * Sc;
            if (Sc >= EPS_CUT) myt0 = (TT - TAILF) + slot;
            Sc *= g;
        }
#pragma unroll
        for (int off = 16; off; off >>= 1) {
            int v = __shfl_xor_sync(0xffffffffu, myt0, off);
            myt0 = v < myt0 ? v : myt0;
        }
        if (l == 0) s_t0 = (myt0 == TT) ? (TT - TAILF) : myt0;
    }
    __syncthreads();

    // ---- P4: accumulation, no barriers ----
    int t0 = s_t0;
    float acc = 0.f;
    for (int t = TT - 1; t >= t0; t--) {
        int slot = t - (TT - TAILF);
        const ulonglong2* ev = (const ulonglong2*)&e_s[slot * ROWS + kq * RQP];
        unsigned long long a0 = 0, a1 = 0, a2 = 0, a3 = 0;
#pragma unroll
        for (int j = 0; j < 16; j += 2) {
            ulonglong2 e0 = ev[j];
            FMA2(a0, wp[2 * j], e0.x);
            FMA2(a1, wp[2 * j + 1], e0.y);
            ulonglong2 e1 = ev[j + 1];
            FMA2(a2, wp[2 * j + 2], e1.x);
            FMA2(a3, wp[2 * j + 3], e1.y);
        }
        float2 f0 = unpack2(a0), f1 = unpack2(a1);
        float2 f2 = unpack2(a2), f3 = unpack2(a3);
        float ps = ((f0.x + f0.y) + (f1.x + f1.y)) +
                   ((f2.x + f2.y) + (f3.x + f3.y));
        ps += __shfl_xor_sync(0xffffffffu, ps, 1);
        ps += __shfl_xor_sync(0xffffffffu, ps, 2);
        acc = fmaf(w_sh[slot], tanhf(ps + wb), acc);
    }

    if ((lane & 3) == 0) d_hT[b * DIM + dg] = acc;
}

// ---------------------------------------------------------------------------
// K2: out[b][v] = hT[b,:].head_w[v,:] + head_b[v]  (packed f32x2).
// As R8 (b split 2, 8v x 4b tile, double-buffered hw chunks) but hT is
// stored PRE-DUPLICATED as (t,t) 8-byte pairs -> per kk just 2 uniform
// LDS.128 (broadcast), no mov.b64 duplication on the FMA2 stream.
// ---------------------------------------------------------------------------
#define HS2 34                      // hTd stride in ulonglong (16B-aligned)
#define WSS 260                     // hws stride (floats)
#define SMEM_HEAD (DIM * HS2 * 8 + 2 * 16 * WSS * 4)

__global__ void __launch_bounds__(256, 2) k_head(
        const float* __restrict__ hw, const float* __restrict__ hb,
        float* __restrict__ out) {
    extern __shared__ float sm[];
    unsigned long long* hTd = (unsigned long long*)sm;   // [256][HS2]
    float* hws0 = sm + DIM * HS2 * 2;                    // [16][WSS]
    float* hws1 = hws0 + 16 * WSS;

    int tid = threadIdx.x;
    int w = tid >> 5, lane = tid & 31;
    int vbase = (blockIdx.x >> 1) * 256;
    int boff = (blockIdx.x & 1) * 32;
    int v0l = lane * 8;
    int b0 = w * 4;

    // hTd[k][b] = (hT,hT) pair (coalesced LDG, one-time)
#pragma unroll
    for (int it = 0; it < 32; it++) {
        int idx = it * 256 + tid;
        int bb = idx >> 8, k = idx & 255;
        hTd[k * HS2 + bb] = dup2(d_hT[(boff + bb) * DIM + k]);
    }
    // stage hw chunk 0
#pragma unroll
    for (int r = 0; r < 16; r++) {
        int idx = r * 256 + tid;
        int vl = idx >> 4, kk = idx & 15;
        hws0[kk * WSS + vl] = hw[(size_t)(vbase + vl) * DIM + kk];
    }
    __syncthreads();

    unsigned long long acc[4][4];
#pragma unroll
    for (int vp = 0; vp < 4; vp++)
#pragma unroll
        for (int bi = 0; bi < 4; bi++) acc[vp][bi] = 0ull;

    for (int ch = 0; ch < 16; ch++) {
        int kb = ch * 16;
        float pf[16];
        if (ch < 15) {
#pragma unroll
            for (int r = 0; r < 16; r++) {
                int idx = r * 256 + tid;
                int vl = idx >> 4, kk = idx & 15;
                pf[r] = hw[(size_t)(vbase + vl) * DIM + kb + 16 + kk];
            }
        }
        const float* buf = (ch & 1) ? hws1 : hws0;
#pragma unroll
        for (int kk = 0; kk < 16; kk++) {
            const unsigned long long* hrow = &hTd[(kb + kk) * HS2 + b0];
            ulonglong2 t01 = *(const ulonglong2*)&hrow[0];
            ulonglong2 t23 = *(const ulonglong2*)&hrow[2];
            unsigned long long td[4] = {t01.x, t01.y, t23.x, t23.y};
            ulonglong2 h01 = *(const ulonglong2*)&buf[kk * WSS + v0l];
            ulonglong2 h23 = *(const ulonglong2*)&buf[kk * WSS + v0l + 4];
            unsigned long long hv2[4] = {h01.x, h01.y, h23.x, h23.y};
#pragma unroll
            for (int vp = 0; vp < 4; vp++)
#pragma unroll
                for (int bi = 0; bi < 4; bi++)
                    FMA2(acc[vp][bi], hv2[vp], td[bi]);
        }
        if (ch < 15) {
            __syncthreads();
            float* dst = (ch & 1) ? hws0 : hws1;
#pragma unroll
            for (int r = 0; r < 16; r++) {
                int idx = r * 256 + tid;
                int vl = idx >> 4, kk = idx & 15;
                dst[kk * WSS + vl] = pf[r];
            }
            __syncthreads();
        }
    }

    // epilogue: float2 stores (v-pairs contiguous), add bias
#pragma unroll
    for (int vp = 0; vp < 4; vp++) {
        int v = vbase + v0l + vp * 2;
        float2 bias = *(const float2*)&hb[v];
#pragma unroll
        for (int bi = 0; bi < 4; bi++) {
            float2 r = unpack2(acc[vp][bi]);
            r.x += bias.x; r.y += bias.y;
            *(float2*)&out[(size_t)(boff + b0 + bi) * VOCAB + v] = r;
        }
    }
}

// ---------------------------------------------------------------------------
extern "C" void kernel_launch(void* const* d_in, const int* in_sizes, int n_in,
                              void* d_out, int out_size) {
    const int*   x      = (const int*)d_in[0];
    const float* emb    = (const float*)d_in[1];
    const float* W_w    = (const float*)d_in[2];
    const float* W_b    = (const float*)d_in[3];
    const float* Wg_w   = (const float*)d_in[4];
    const float* Wg_b   = (const float*)d_in[5];
    const float* head_w = (const float*)d_in[6];
    const float* head_b = (const float*)d_in[7];
    float* out = (float*)d_out;

    cudaFuncSetAttribute(k_fused, cudaFuncAttributeMaxDynamicSharedMemorySize,
                         DSMEM_F);
    k_fused<<<dim3(2, BB), 512, DSMEM_F>>>(x, emb, W_w, W_b, Wg_w, Wg_b);
    cudaFuncSetAttribute(k_head, cudaFuncAttributeMaxDynamicSharedMemorySize,
                         SMEM_HEAD);
    k_head<<<250, 256, SMEM_HEAD>>>(head_w, head_b, out);
}

// round 13
// speedup vs baseline: 2.1171x; 1.4087x over previous
#include <cuda_runtime.h>
#include <cuda_bf16.h>
#include <math.h>
#include <stdint.h>

#define BB 64
#define TT 2048
#define DIM 256
#define VOCAB 32000
#define TAILF 96
#define EPS_CUT 1e-7f

__device__ float d_hT[BB * DIM];   // [b][k] fp32

// packed f32x2 FMA: c = a*b + c (elementwise on 2 packed fp32)
#define FMA2(c, a, b) \
    asm("fma.rn.f32x2 %0, %1, %2, %0;" : "+l"(c) : "l"(a), "l"(b))
__device__ __forceinline__ float2 unpack2(unsigned long long v) {
    float2 r;
    asm("mov.b64 {%0,%1}, %2;" : "=f"(r.x), "=f"(r.y) : "l"(v));
    return r;
}
__device__ __forceinline__ unsigned long long dup2(float s) {
    unsigned long long d;
    asm("mov.b64 %0, {%1,%1};" : "=l"(d) : "f"(s));
    return d;
}

// ---------------------------------------------------------------------------
// K1 (fused scan+main) — unchanged from the 84.7us round.
// ---------------------------------------------------------------------------
#define RQP 68
#define ROWS 272
#define DSMEM_F (TAILF * ROWS * 4)

__global__ void __launch_bounds__(512, 1) k_fused(
        const int* __restrict__ x, const float* __restrict__ emb,
        const float* __restrict__ W, const float* __restrict__ Wb,
        const float* __restrict__ Wg, const float* __restrict__ Wg_b) {
    extern __shared__ float e_s[];             // [96][272]
    __shared__ float g_sh[TAILF], w_sh[TAILF];
    __shared__ int s_x[TAILF];
    __shared__ int s_t0;

    int dh = blockIdx.x, b = blockIdx.y, tid = threadIdx.x;
    int lane = tid & 31, w = tid >> 5;
    int kq = lane & 3;
    int dg = dh * 128 + w * 8 + (lane >> 2);

    unsigned long long wp[32];
    const ulonglong2* W2 = (const ulonglong2*)(W + (size_t)dg * DIM + kq * 64);
#pragma unroll
    for (int i = 0; i < 16; i++) {
        ulonglong2 v = W2[i];
        wp[2 * i] = v.x; wp[2 * i + 1] = v.y;
    }
    float wb = Wb[dg];
    float gb = Wg_b[0];
    float4 wg0 = ((const float4*)Wg)[lane * 2];
    float4 wg1 = ((const float4*)Wg)[lane * 2 + 1];

    if (tid < TAILF) s_x[tid] = x[b * TT + (TT - TAILF) + tid];
    __syncthreads();

#pragma unroll
    for (int it = 0; it < 12; it++) {
        int idx4 = it * 512 + tid;
        int r = idx4 >> 6, c4 = idx4 & 63;
        float4 v = *(const float4*)&emb[(size_t)s_x[r] * DIM + c4 * 4];
        *(float4*)&e_s[r * ROWS + (c4 >> 4) * RQP + (c4 & 15) * 4] = v;
    }
    __syncthreads();

#pragma unroll
    for (int j = 0; j < 6; j++) {
        int r = w * 6 + j;
        const float* row = &e_s[r * ROWS + (lane >> 3) * RQP + ((lane * 8) & 63)];
        float4 a0 = *(const float4*)row;
        float4 a1 = *(const float4*)(row + 4);
        float z = a0.x * wg0.x + a0.y * wg0.y + a0.z * wg0.z + a0.w * wg0.w
                + a1.x * wg1.x + a1.y * wg1.y + a1.z * wg1.z + a1.w * wg1.w;
#pragma unroll
        for (int off = 16; off; off >>= 1)
            z += __shfl_xor_sync(0xffffffffu, z, off);
        if (lane == 0) g_sh[r] = 1.f / (1.f + expf(-(z + gb)));
    }
    __syncthreads();

    if (tid < 32) {
        int l = tid;
        float P = g_sh[l * 3] * g_sh[l * 3 + 1] * g_sh[l * 3 + 2];
        float S = P;
#pragma unroll
        for (int off = 1; off < 32; off <<= 1) {
            float v = __shfl_down_sync(0xffffffffu, S, off);
            if (l + off < 32) S *= v;
        }
        float Q = __shfl_down_sync(0xffffffffu, S, 1);
        if (l == 31) Q = 1.f;
        float Sc = Q;
        int myt0 = TT;
#pragma unroll
        for (int j = 2; j >= 0; j--) {
            int slot = l * 3 + j;
            float g = g_sh[slot];
            w_sh[slot] = (1.f - g) * Sc;
            if (Sc >= EPS_CUT) myt0 = (TT - TAILF) + slot;
            Sc *= g;
        }
#pragma unroll
        for (int off = 16; off; off >>= 1) {
            int v = __shfl_xor_sync(0xffffffffu, myt0, off);
            myt0 = v < myt0 ? v : myt0;
        }
        if (l == 0) s_t0 = (myt0 == TT) ? (TT - TAILF) : myt0;
    }
    __syncthreads();

    int t0 = s_t0;
    float acc = 0.f;
    for (int t = TT - 1; t >= t0; t--) {
        int slot = t - (TT - TAILF);
        const ulonglong2* ev = (const ulonglong2*)&e_s[slot * ROWS + kq * RQP];
        unsigned long long a0 = 0, a1 = 0, a2 = 0, a3 = 0;
#pragma unroll
        for (int j = 0; j < 16; j += 2) {
            ulonglong2 e0 = ev[j];
            FMA2(a0, wp[2 * j], e0.x);
            FMA2(a1, wp[2 * j + 1], e0.y);
            ulonglong2 e1 = ev[j + 1];
            FMA2(a2, wp[2 * j + 2], e1.x);
            FMA2(a3, wp[2 * j + 3], e1.y);
        }
        float2 f0 = unpack2(a0), f1 = unpack2(a1);
        float2 f2 = unpack2(a2), f3 = unpack2(a3);
        float ps = ((f0.x + f0.y) + (f1.x + f1.y)) +
                   ((f2.x + f2.y) + (f3.x + f3.y));
        ps += __shfl_xor_sync(0xffffffffu, ps, 1);
        ps += __shfl_xor_sync(0xffffffffu, ps, 2);
        acc = fmaf(w_sh[slot], tanhf(ps + wb), acc);
    }

    if ((lane & 3) == 0) d_hT[b * DIM + dg] = acc;
}

// ---------------------------------------------------------------------------
// K2: out[b][v] = hT[b,:].head_w[v,:] + head_b[v]  (packed f32x2).
// 125 CTAs: block = 256 v x ALL 64 b; warp = 256 v x 8 b (b0 = w*8);
// thread tile 8 v x 8 b = 32 FFMA2/kk.
// hws rows = exactly 1024B; 16B-granule swizzle j^=((j>>3)&7) makes the
// lane*8-stride LDS.128s conflict-free (4 phases). hT read as 2 uniform
// float4 + in-reg dup (ALU pipe). FMA-bound by design (LDS 80 vs FMA 128
// cyc per kk per SM).
// ---------------------------------------------------------------------------
#define HS 68                        // hTs stride (floats), 16B-aligned
#define WSS 260                      // hws row stride (floats) = 1040B
#define SMEM_HEAD ((DIM * HS + 2 * 16 * WSS) * 4)

__device__ __forceinline__ int swg(int j) { return j ^ ((j >> 3) & 7); }

__global__ void __launch_bounds__(256, 1) k_head(
        const float* __restrict__ hw, const float* __restrict__ hb,
        float* __restrict__ out) {
    extern __shared__ float sm[];
    float* hTs = sm;                   // [256][HS] (64 b + pad)
    float* hws0 = sm + DIM * HS;       // [16][WSS]
    float* hws1 = hws0 + 16 * WSS;

    int tid = threadIdx.x;
    int w = tid >> 5, lane = tid & 31;
    int vbase = blockIdx.x * 256;
    int b0 = w * 8;
    // precomputed swizzled float-offsets for this lane's two 16B granules
    int p0 = swg(2 * lane) * 4;
    int p1 = swg(2 * lane + 1) * 4;

    // hTs[k][b]: coalesced LDG (one-time)
#pragma unroll
    for (int it = 0; it < 64; it++) {
        int idx = it * 256 + tid;
        int bb = idx >> 8, k = idx & 255;
        hTs[k * HS + bb] = d_hT[bb * DIM + k];
    }
    // stage hw chunk 0 (swizzled)
#pragma unroll
    for (int r = 0; r < 16; r++) {
        int idx = r * 256 + tid;
        int vl = idx >> 4, kk = idx & 15;
        hws0[kk * WSS + swg(vl >> 2) * 4 + (vl & 3)] =
            hw[(size_t)(vbase + vl) * DIM + kk];
    }
    __syncthreads();

    unsigned long long acc[4][8];
#pragma unroll
    for (int vp = 0; vp < 4; vp++)
#pragma unroll
        for (int bi = 0; bi < 8; bi++) acc[vp][bi] = 0ull;

    for (int ch = 0; ch < 16; ch++) {
        int kb = ch * 16;
        float pf[16];
        if (ch < 15) {
#pragma unroll
            for (int r = 0; r < 16; r++) {
                int idx = r * 256 + tid;
                int vl = idx >> 4, kk = idx & 15;
                pf[r] = hw[(size_t)(vbase + vl) * DIM + kb + 16 + kk];
            }
        }
        const float* buf = (ch & 1) ? hws1 : hws0;
#pragma unroll
        for (int kk = 0; kk < 16; kk++) {
            const float* base = buf + kk * WSS;
            ulonglong2 h01 = *(const ulonglong2*)(base + p0);
            ulonglong2 h23 = *(const ulonglong2*)(base + p1);
            unsigned long long hv2[4] = {h01.x, h01.y, h23.x, h23.y};
            const float* hrow = &hTs[(kb + kk) * HS + b0];
            float4 t0 = *(const float4*)hrow;
            float4 t1 = *(const float4*)(hrow + 4);
            unsigned long long td[8] = {dup2(t0.x), dup2(t0.y), dup2(t0.z),
                                        dup2(t0.w), dup2(t1.x), dup2(t1.y),
                                        dup2(t1.z), dup2(t1.w)};
#pragma unroll
            for (int vp = 0; vp < 4; vp++)
#pragma unroll
                for (int bi = 0; bi < 8; bi++)
                    FMA2(acc[vp][bi], hv2[vp], td[bi]);
        }
        if (ch < 15) {
            __syncthreads();
            float* dst = (ch & 1) ? hws0 : hws1;
#pragma unroll
            for (int r = 0; r < 16; r++) {
                int idx = r * 256 + tid;
                int vl = idx >> 4, kk = idx & 15;
                dst[kk * WSS + swg(vl >> 2) * 4 + (vl & 3)] = pf[r];
            }
            __syncthreads();
        }
    }

    // epilogue: float2 stores (v-pairs contiguous), add bias
#pragma unroll
    for (int vp = 0; vp < 4; vp++) {
        int v = vbase + lane * 8 + vp * 2;
        float2 bias = *(const float2*)&hb[v];
#pragma unroll
        for (int bi = 0; bi < 8; bi++) {
            float2 r = unpack2(acc[vp][bi]);
            r.x += bias.x; r.y += bias.y;
            *(float2*)&out[(size_t)(b0 + bi) * VOCAB + v] = r;
        }
    }
}

// ---------------------------------------------------------------------------
extern "C" void kernel_launch(void* const* d_in, const int* in_sizes, int n_in,
                              void* d_out, int out_size) {
    const int*   x      = (const int*)d_in[0];
    const float* emb    = (const float*)d_in[1];
    const float* W_w    = (const float*)d_in[2];
    const float* W_b    = (const float*)d_in[3];
    const float* Wg_w   = (const float*)d_in[4];
    const float* Wg_b   = (const float*)d_in[5];
    const float* head_w = (const float*)d_in[6];
    const float* head_b = (const float*)d_in[7];
    float* out = (float*)d_out;

    cudaFuncSetAttribute(k_fused, cudaFuncAttributeMaxDynamicSharedMemorySize,
                         DSMEM_F);
    k_fused<<<dim3(2, BB), 512, DSMEM_F>>>(x, emb, W_w, W_b, Wg_w, Wg_b);
    cudaFuncSetAttribute(k_head, cudaFuncAttributeMaxDynamicSharedMemorySize,
                         SMEM_HEAD);
    k_head<<<VOCAB / 256, 256, SMEM_HEAD>>>(head_w, head_b, out);
}